// round 15
// baseline (speedup 1.0000x reference)
#include <cuda_runtime.h>
#include <cuda_bf16.h>
#include <cuda_fp16.h>
#include <math.h>
#include <stdint.h>

#define BB 2
#define SS 2048
#define DD 2048
#define HH 32
#define DH 64
#define MM (BB*SS)   // 4096

// ---------------- scratch (device globals; no allocations allowed) ----------
__device__ float g_cos[SS*32];
__device__ float g_sin[SS*32];
// attention operands (fp16/bf16, head-transposed [B,H,S,Dh])
__device__ __half g_q16[(size_t)BB*HH*SS*DH];         // q (x1/8), roped
__device__ __half g_k16[(size_t)BB*HH*SS*DH];         // k, roped
__device__ __nv_bfloat16 g_vb[(size_t)BB*HH*SS*DH];   // sigmoid(v), bf16
// GEMM operands (plain fp16)
__device__ __half g_xh[(size_t)MM * DD];
__device__ __half g_yh[(size_t)MM * DD];
__device__ __half g_wh[4][(size_t)DD * DD];

#define SMEM_SWIZZLE_128B(off) ((off) ^ (((off) >> 3) & 0x70))

__device__ __forceinline__ uint32_t smem_u32(const void* p) {
    uint32_t a;
    asm("{ .reg .u64 t; cvta.to.shared.u64 t, %1; cvt.u32.u64 %0, t; }"
        : "=r"(a) : "l"(p));
    return a;
}
__device__ __forceinline__ void cp_async16(uint32_t saddr, const void* gaddr) {
    asm volatile("cp.async.cg.shared.global [%0], [%1], 16;"
                 :: "r"(saddr), "l"(gaddr) : "memory");
}
#define CP_COMMIT() asm volatile("cp.async.commit_group;" ::: "memory")
#define CP_WAIT1()  asm volatile("cp.async.wait_group 1;" ::: "memory")

__device__ __forceinline__ void ldm_x4(uint32_t* r, uint32_t addr) {
    asm volatile("ldmatrix.sync.aligned.m8n8.x4.shared.b16 {%0,%1,%2,%3}, [%4];"
                 : "=r"(r[0]), "=r"(r[1]), "=r"(r[2]), "=r"(r[3]) : "r"(addr));
}
__device__ __forceinline__ void ldm_x4_trans(uint32_t* r, uint32_t addr) {
    asm volatile("ldmatrix.sync.aligned.m8n8.x4.trans.shared.b16 {%0,%1,%2,%3}, [%4];"
                 : "=r"(r[0]), "=r"(r[1]), "=r"(r[2]), "=r"(r[3]) : "r"(addr));
}
__device__ __forceinline__ void mma16816(float* c, const uint32_t* a, const uint32_t* b) {
    asm volatile(
        "mma.sync.aligned.m16n8k16.row.col.f32.bf16.bf16.f32 "
        "{%0,%1,%2,%3}, {%4,%5,%6,%7}, {%8,%9}, {%0,%1,%2,%3};"
        : "+f"(c[0]), "+f"(c[1]), "+f"(c[2]), "+f"(c[3])
        : "r"(a[0]), "r"(a[1]), "r"(a[2]), "r"(a[3]), "r"(b[0]), "r"(b[1]));
}
__device__ __forceinline__ void mma16816h(float* c, const uint32_t* a, const uint32_t* b) {
    asm volatile(
        "mma.sync.aligned.m16n8k16.row.col.f32.f16.f16.f32 "
        "{%0,%1,%2,%3}, {%4,%5,%6,%7}, {%8,%9}, {%0,%1,%2,%3};"
        : "+f"(c[0]), "+f"(c[1]), "+f"(c[2]), "+f"(c[3])
        : "r"(a[0]), "r"(a[1]), "r"(a[2]), "r"(a[3]), "r"(b[0]), "r"(b[1]));
}
__device__ __forceinline__ float ex2f(float x) {
    float y; asm("ex2.approx.ftz.f32 %0, %1;" : "=f"(y) : "f"(x)); return y;
}
__device__ __forceinline__ uint32_t packbf(float lo, float hi) {
    uint32_t r;
    asm("cvt.rn.bf16x2.f32 %0, %1, %2;" : "=r"(r) : "f"(hi), "f"(lo));
    return r;
}

// ---------------- RoPE table (fp64 for accuracy) ----------------------------
__global__ void rope_table_kernel() {
    int idx = blockIdx.x * blockDim.x + threadIdx.x;
    if (idx >= SS * 32) return;
    int s = idx >> 5;
    int p = idx & 31;
    double invf = exp(-(double)p * (log(10000.0) / 32.0));
    double ang = (double)s * invf;
    g_cos[idx] = (float)cos(ang);
    g_sin[idx] = (float)sin(ang);
}

// ---------------- fused fp32 -> fp16 converts (x + 4 weights) ----------------
// 4 float4 per thread (MLP=4). Segments: 0..3 = weights (M4 float4 each),
// 4..5 = x (2*M4 float4 total; offset relative to seg 4 start!).
#define M4 (DD * DD / 4)
__global__ void __launch_bounds__(256) convert_all_kernel(
    const float* __restrict__ x,  const float* __restrict__ Wq,
    const float* __restrict__ Wk, const float* __restrict__ Wv,
    const float* __restrict__ Wo)
{
    int id = blockIdx.x * blockDim.x + threadIdx.x;     // < 6*M4/4
    if (id >= 6 * M4 / 4) return;
    int base4 = id * 4;                                  // float4 index
    int seg = base4 / M4;                                // chunks never straddle
    const float* src;
    __half* dst;
    size_t off;
    if (seg < 4) {
        off = (size_t)(base4 - seg * M4);
        src = (seg == 0) ? Wq : (seg == 1) ? Wk : (seg == 2) ? Wv : Wo;
        dst = g_wh[seg];
    } else {
        off = (size_t)(base4 - 4 * M4);                  // x spans segs 4..5
        src = x;
        dst = g_xh;
    }
    float4 v[4];
#pragma unroll
    for (int j = 0; j < 4; j++)
        v[j] = *(const float4*)(src + (off + j) * 4);
#pragma unroll
    for (int j = 0; j < 4; j++) {
        uint2 u;
        u.x = (uint32_t)__half_as_ushort(__float2half(v[j].x)) |
              ((uint32_t)__half_as_ushort(__float2half(v[j].y)) << 16);
        u.y = (uint32_t)__half_as_ushort(__float2half(v[j].z)) |
              ((uint32_t)__half_as_ushort(__float2half(v[j].w)) << 16);
        *(uint2*)(dst + (off + j) * 4) = u;
    }
}

// ---------------- HMMA fp16 1-term GEMM, CTA 256x128, warp tile 64x64 --------
// FUSED=1: QKV — grid.z selects {Wq->rope->q16(x1/8), Wk->rope->k16,
//                                Wv->sigmoid->vb}; RoPE fused in epilogue.
// FUSED=0: O   — A=g_yh, W=g_wh[3], fp32 store to Cext with bias b0p.
#define KSTAGES 32
#define GSTAGE 49152u                // A 32KB (256x128B) + B 16KB (128x128B)
#define GEMM_SMEM (2 * GSTAGE)

template<int FUSED>
__global__ void __launch_bounds__(256, 1) gemm_tc_kernel(
    const float* __restrict__ b0p, const float* __restrict__ b1p,
    const float* __restrict__ b2p, float* __restrict__ Cext)
{
    extern __shared__ char smem[];
    const uint32_t sb = smem_u32(smem);
    const int tid  = threadIdx.x;
    const int wid  = tid >> 5;
    const int lane = tid & 31;
    const int n0 = blockIdx.x << 7;
    const int m0 = blockIdx.y << 8;          // 256-row tiles
    const int wm = (wid >> 1) * 64;          // 4 warp rows
    const int wn = (wid & 1) * 64;           // 2 warp cols (one head each)

    int mode, widx;
    const float* bias;
    if (FUSED) {
        widx = blockIdx.z;
        mode = widx + 1;
        bias = (widx == 0) ? b0p : (widx == 1) ? b1p : b2p;
    } else {
        widx = 3; mode = 0; bias = b0p;
    }

    const __half* __restrict__ Ah = FUSED ? g_xh : g_yh;
    const __half* __restrict__ Wh = g_wh[widx];

    float acc[4][8][4];
#pragma unroll
    for (int i = 0; i < 4; i++)
#pragma unroll
        for (int j = 0; j < 8; j++)
#pragma unroll
            for (int t = 0; t < 4; t++) acc[i][j][t] = 0.f;

    auto issue_stage = [&](int s) {
        uint32_t base = sb + (uint32_t)(s & 1) * GSTAGE;
#pragma unroll
        for (int i = 0; i < 8; i++) {
            int c   = tid + (i << 8);
            int row = c >> 3;
            int col = c & 7;
            uint32_t off = SMEM_SWIZZLE_128B((uint32_t)(row * 128 + col * 16));
            cp_async16(base + off,
                       Ah + (size_t)(m0 + row) * DD + s * 64 + col * 8);
        }
#pragma unroll
        for (int i = 0; i < 4; i++) {
            int c   = tid + (i << 8);
            int row = c >> 3;
            int col = c & 7;
            uint32_t off = SMEM_SWIZZLE_128B((uint32_t)(row * 128 + col * 16));
            cp_async16(base + 32768 + off,
                       Wh + (size_t)(n0 + row) * DD + s * 64 + col * 8);
        }
    };

    issue_stage(0); CP_COMMIT();
    issue_stage(1); CP_COMMIT();

    const int a_row = (lane & 15);
    const int a_colsel = (lane >> 4) << 4;
    const int b_row = (lane & 7) + ((lane >> 4) << 3);
    const int b_colsel = ((lane >> 3) & 1) << 4;

    for (int s = 0; s < KSTAGES; s++) {
        CP_WAIT1();
        __syncthreads();
        const uint32_t sA = sb + (uint32_t)(s & 1) * GSTAGE;
        const uint32_t sB = sA + 32768;

#pragma unroll
        for (int ks = 0; ks < 4; ks++) {
            uint32_t ah[4][4], bh[8][2];
#pragma unroll
            for (int mi = 0; mi < 4; mi++) {
                uint32_t rbase = (uint32_t)((wm + mi * 16 + a_row) * 128);
                ldm_x4(ah[mi], sA + SMEM_SWIZZLE_128B(rbase + ks * 32 + a_colsel));
            }
#pragma unroll
            for (int p = 0; p < 4; p++) {
                uint32_t brel = (uint32_t)((wn + p * 16 + b_row) * 128 + ks * 32 + b_colsel);
                uint32_t tb[4];
                ldm_x4(tb, sB + SMEM_SWIZZLE_128B(brel));
                bh[2*p][0] = tb[0]; bh[2*p][1] = tb[1];
                bh[2*p+1][0] = tb[2]; bh[2*p+1][1] = tb[3];
            }
#pragma unroll
            for (int mi = 0; mi < 4; mi++)
#pragma unroll
                for (int ni = 0; ni < 8; ni++)
                    mma16816h(acc[mi][ni], ah[mi], bh[ni]);
        }
        __syncthreads();
        if (s + 2 < KSTAGES) issue_stage(s + 2);
        CP_COMMIT();
    }

    // ---------------- epilogue ------------------------------------------------
    if (FUSED && mode <= 2) {
        __half* dst = (mode == 1) ? g_q16 : g_k16;
        const float qs = (mode == 1) ? 0.125f : 1.f;
#pragma unroll
        for (int mi = 0; mi < 4; mi++) {
#pragma unroll
            for (int half = 0; half < 2; half++) {
                int m = m0 + wm + mi * 16 + (lane >> 2) + half * 8;
                int bb = m >> 11, srow = m & (SS - 1);
#pragma unroll
                for (int ni = 0; ni < 4; ni++) {
                    int n = n0 + wn + ni * 8 + 2 * (lane & 3);
                    int hh = n >> 6, d = n & 63;
                    int ti = (srow << 5) + d;
                    float c0 = __ldg(g_cos + ti),     sn0 = __ldg(g_sin + ti);
                    float c1 = __ldg(g_cos + ti + 1), sn1 = __ldg(g_sin + ti + 1);
                    float a0 = acc[mi][ni][2*half]       + __ldg(bias + n);
                    float a1 = acc[mi][ni][2*half + 1]   + __ldg(bias + n + 1);
                    float e0 = acc[mi][ni+4][2*half]     + __ldg(bias + n + 32);
                    float e1 = acc[mi][ni+4][2*half + 1] + __ldg(bias + n + 33);
                    size_t o = ((size_t)(bb * HH + hh) * SS + srow) * DH + d;
                    *(__half2*)(dst + o) =
                        __floats2half2_rn((a0*c0 - e0*sn0) * qs, (a1*c1 - e1*sn1) * qs);
                    *(__half2*)(dst + o + 32) =
                        __floats2half2_rn((e0*c0 + a0*sn0) * qs, (e1*c1 + a1*sn1) * qs);
                }
            }
        }
    } else {
#pragma unroll
        for (int mi = 0; mi < 4; mi++) {
#pragma unroll
            for (int ni = 0; ni < 8; ni++) {
                int n = n0 + wn + ni * 8 + 2 * (lane & 3);
                float b0 = __ldg(bias + n);
                float b1 = __ldg(bias + n + 1);
#pragma unroll
                for (int half = 0; half < 2; half++) {
                    int m = m0 + wm + mi * 16 + (lane >> 2) + half * 8;
                    float v0 = acc[mi][ni][2 * half]     + b0;
                    float v1 = acc[mi][ni][2 * half + 1] + b1;
                    if (mode == 0) {
                        Cext[(size_t)m * DD + n]     = v0;
                        Cext[(size_t)m * DD + n + 1] = v1;
                    } else {   // mode 3: sigmoid -> vb
                        int bb = m >> 11, srow = m & (SS - 1);
                        int hh = n >> 6, d = n & 63;
                        size_t o = ((size_t)(bb * HH + hh) * SS + srow) * DH + d;
                        v0 = 1.f / (1.f + __expf(-v0));
                        v1 = 1.f / (1.f + __expf(-v1));
                        __nv_bfloat162 t2;
                        t2.x = __float2bfloat16(v0);
                        t2.y = __float2bfloat16(v1);
                        *(__nv_bfloat162*)(g_vb + o) = t2;
                    }
                }
            }
        }
    }
}

// ---------------- tensor-core flash attention --------------------------------
// CTA: 128 q rows, 128 threads; 4 warps x 32 rows (2 m-tiles of 16).
// Inner loop fused per 16-key block: QK(kb) -> exp(kb) -> PV(kb), so
// consecutive kb iterations overlap (short dependency chains, high ILP).
// Q fragments hoisted out of the tile loop (loop-invariant).
// QK: fp16 1-term; PV: bf16. smem: Q 16KB @0; tiles (k 8K|v 8K) dbl-buffered.
#define ATT_SMEM (16384 + 2 * 16384)
#define L2E 1.4426950408889634f
#define SH20 28.853900817779268f

__global__ void __launch_bounds__(128, 1) attn_tc_kernel() {
    extern __shared__ char smem[];
    const uint32_t sb = smem_u32(smem);
    const int tid  = threadIdx.x;
    const int wid  = tid >> 5;
    const int lane = tid & 31;
    const int bh = blockIdx.y;
    const int q0 = (gridDim.x - 1 - blockIdx.x) << 7;   // heavy CTAs first
    const int b  = bh >> 5;
    const int h  = bh & 31;
    const size_t rowbase = (size_t)bh * SS;
    const int wm = wid << 5;                 // 32 rows per warp

    auto issue_tile = [&](int t) {
        int j0 = t << 6;
        uint32_t base = sb + 16384 + (t & 1) * 16384;
#pragma unroll
        for (int i = 0; i < 4; i++) {
            int c = tid * 4 + i;
            int row = c >> 3, col = c & 7;
            uint32_t off = SMEM_SWIZZLE_128B((uint32_t)(row * 128 + col * 16));
            size_t g = (rowbase + j0 + row) * DH + col * 8;
            cp_async16(base + off,        g_k16 + g);
            cp_async16(base + 8192 + off, g_vb + g);
        }
    };

    // Q: 128 rows x 128B = 16KB, 1024 chunks, 8 per thread
#pragma unroll
    for (int i = 0; i < 8; i++) {
        int c = tid * 8 + i;
        int row = c >> 3, col = c & 7;
        uint32_t off = SMEM_SWIZZLE_128B((uint32_t)(row * 128 + col * 16));
        cp_async16(sb + off, g_q16 + (rowbase + q0 + row) * DH + col * 8);
    }
    issue_tile(0); CP_COMMIT();
    const int nt = (q0 >> 6) + 2;
    issue_tile(1); CP_COMMIT();

    float o[2][8][4];
#pragma unroll
    for (int mi = 0; mi < 2; mi++)
#pragma unroll
        for (int nf = 0; nf < 8; nf++)
#pragma unroll
            for (int i = 0; i < 4; i++) o[mi][nf][i] = 0.f;
    float l[2][2] = {{0.f, 0.f}, {0.f, 0.f}};

    const int a_rc  = (lane & 15) * 128 + ((lane >> 4) << 4);
    const int b_rc  = ((lane & 7) + ((lane >> 4) << 3)) * 128 + (((lane >> 3) & 1) << 4);
    const int v_rc  = (lane & 15) * 128 + ((lane >> 4) << 4);
    const int r0    = q0 + wm + (lane >> 2);     // m-tile 0 rows: r0, r0+8; tile 1: +16,+24

    uint32_t q4[2][4][4];          // hoisted Q fragments [mi][ks][4]
    bool qload = false;

    for (int t = 0; t < nt; t++) {
        CP_WAIT1();
        __syncthreads();
        if (!qload) {              // Q arrived with group0; load once
            qload = true;
#pragma unroll
            for (int mi = 0; mi < 2; mi++)
#pragma unroll
                for (int ks = 0; ks < 4; ks++)
                    ldm_x4(q4[mi][ks], sb + SMEM_SWIZZLE_128B(
                        (uint32_t)((wm + mi * 16) * 128 + a_rc + ks * 32)));
        }
        const uint32_t sK = sb + 16384 + (t & 1) * 16384;
        if ((t << 6) <= q0 + wm + 31) {
            const bool unmasked = ((t << 6) + 63 <= q0 + wm);
            const int jb = (t << 6) + ((lane & 3) << 1);
#pragma unroll
            for (int kb = 0; kb < 4; kb++) {
                // ---- QK for this 16-key block ----
                float s[2][2][4];
#pragma unroll
                for (int mi = 0; mi < 2; mi++)
#pragma unroll
                    for (int half = 0; half < 2; half++)
#pragma unroll
                        for (int i = 0; i < 4; i++) s[mi][half][i] = 0.f;
#pragma unroll
                for (int ks = 0; ks < 4; ks++) {
                    uint32_t kh4[4];
                    uint32_t brel = (uint32_t)(kb * 2048 + b_rc + ks * 32);
                    ldm_x4(kh4, sK + SMEM_SWIZZLE_128B(brel));
#pragma unroll
                    for (int mi = 0; mi < 2; mi++) {
                        mma16816h(s[mi][0], q4[mi][ks], &kh4[0]);
                        mma16816h(s[mi][1], q4[mi][ks], &kh4[2]);
                    }
                }
                // ---- exp + pack ----
                uint32_t pk[2][2][2];
#pragma unroll
                for (int mi = 0; mi < 2; mi++) {
                    int rm = r0 + mi * 16;
#pragma unroll
                    for (int half = 0; half < 2; half++) {
                        int j = jb + (2 * kb + half) * 8;
                        float p0, p1, p2, p3;
                        if (unmasked) {
                            p0 = ex2f(fmaf(s[mi][half][0], L2E, -SH20));
                            p1 = ex2f(fmaf(s[mi][half][1], L2E, -SH20));
                            p2 = ex2f(fmaf(s[mi][half][2], L2E, -SH20));
                            p3 = ex2f(fmaf(s[mi][half][3], L2E, -SH20));
                        } else {
                            p0 = (j     <= rm)     ? ex2f(fmaf(s[mi][half][0], L2E, -SH20)) : 0.f;
                            p1 = (j + 1 <= rm)     ? ex2f(fmaf(s[mi][half][1], L2E, -SH20)) : 0.f;
                            p2 = (j     <= rm + 8) ? ex2f(fmaf(s[mi][half][2], L2E, -SH20)) : 0.f;
                            p3 = (j + 1 <= rm + 8) ? ex2f(fmaf(s[mi][half][3], L2E, -SH20)) : 0.f;
                        }
                        l[mi][0] += p0 + p1;
                        l[mi][1] += p2 + p3;
                        pk[mi][half][0] = packbf(p0, p1);
                        pk[mi][half][1] = packbf(p2, p3);
                    }
                }
                // ---- PV for this key block ----
#pragma unroll
                for (int cb = 0; cb < 4; cb++) {
                    uint32_t vf[4];
                    uint32_t vrel = (uint32_t)(kb * 2048 + v_rc + cb * 32);
                    ldm_x4_trans(vf, sK + 8192 + SMEM_SWIZZLE_128B(vrel));
#pragma unroll
                    for (int mi = 0; mi < 2; mi++) {
                        uint32_t a[4] = {pk[mi][0][0], pk[mi][0][1],
                                         pk[mi][1][0], pk[mi][1][1]};
                        mma16816(o[mi][2*cb],   a, &vf[0]);
                        mma16816(o[mi][2*cb+1], a, &vf[2]);
                    }
                }
            }
        }
        __syncthreads();
        if (t + 2 < nt) issue_tile(t + 2);
        CP_COMMIT();
    }

#pragma unroll
    for (int mi = 0; mi < 2; mi++) {
        l[mi][0] += __shfl_xor_sync(0xffffffffu, l[mi][0], 1);
        l[mi][0] += __shfl_xor_sync(0xffffffffu, l[mi][0], 2);
        l[mi][1] += __shfl_xor_sync(0xffffffffu, l[mi][1], 1);
        l[mi][1] += __shfl_xor_sync(0xffffffffu, l[mi][1], 2);
        float inv0 = 1.f / l[mi][0], inv1 = 1.f / l[mi][1];
        int rm = r0 + mi * 16;
#pragma unroll
        for (int nf = 0; nf < 8; nf++) {
            int d = h * 64 + nf * 8 + ((lane & 3) << 1);
            __half2 w0 = __floats2half2_rn(o[mi][nf][0] * inv0, o[mi][nf][1] * inv0);
            __half2 w1 = __floats2half2_rn(o[mi][nf][2] * inv1, o[mi][nf][3] * inv1);
            *(__half2*)&g_yh[((size_t)b * SS + rm)     * DD + d] = w0;
            *(__half2*)&g_yh[((size_t)b * SS + rm + 8) * DD + d] = w1;
        }
    }
}

// ---------------- launch ------------------------------------------------------
extern "C" void kernel_launch(void* const* d_in, const int* in_sizes, int n_in,
                              void* d_out, int out_size) {
    (void)in_sizes; (void)n_in; (void)out_size;
    const float* x  = (const float*)d_in[0];
    const float* Wq = (const float*)d_in[1];
    const float* bq = (const float*)d_in[2];
    const float* Wk = (const float*)d_in[3];
    const float* bk = (const float*)d_in[4];
    const float* Wv = (const float*)d_in[5];
    const float* bv = (const float*)d_in[6];
    const float* Wo = (const float*)d_in[7];
    const float* bo = (const float*)d_in[8];
    float* out = (float*)d_out;

    cudaFuncSetAttribute((const void*)gemm_tc_kernel<1>,
                         cudaFuncAttributeMaxDynamicSharedMemorySize, GEMM_SMEM);
    cudaFuncSetAttribute((const void*)gemm_tc_kernel<0>,
                         cudaFuncAttributeMaxDynamicSharedMemorySize, GEMM_SMEM);
    cudaFuncSetAttribute((const void*)attn_tc_kernel,
                         cudaFuncAttributeMaxDynamicSharedMemorySize, ATT_SMEM);

    rope_table_kernel<<<(SS * 32 + 255) / 256, 256>>>();
    convert_all_kernel<<<(6 * M4 / 4 + 255) / 256, 256>>>(x, Wq, Wk, Wv, Wo);

    dim3 qkv_grid(DD / 128, MM / 256, 3);
    gemm_tc_kernel<1><<<qkv_grid, 256, GEMM_SMEM>>>(bq, bk, bv, nullptr);

    attn_tc_kernel<<<dim3(SS / 128, BB * HH), 128, ATT_SMEM>>>();

    dim3 o_grid(DD / 128, MM / 256, 1);
    gemm_tc_kernel<0><<<o_grid, 256, GEMM_SMEM>>>(bo, nullptr, nullptr, out);
}

// round 16
// speedup vs baseline: 1.0111x; 1.0111x over previous
#include <cuda_runtime.h>
#include <cuda_bf16.h>
#include <cuda_fp16.h>
#include <math.h>
#include <stdint.h>

#define BB 2
#define SS 2048
#define DD 2048
#define HH 32
#define DH 64
#define MM (BB*SS)   // 4096

// ---------------- scratch (device globals; no allocations allowed) ----------
__device__ float g_cos[SS*32];
__device__ float g_sin[SS*32];
// attention operands (fp16/bf16, head-transposed [B,H,S,Dh])
__device__ __half g_q16[(size_t)BB*HH*SS*DH];         // q (x1/8), roped
__device__ __half g_k16[(size_t)BB*HH*SS*DH];         // k, roped
__device__ __nv_bfloat16 g_vb[(size_t)BB*HH*SS*DH];   // sigmoid(v), bf16
// GEMM operands (plain fp16)
__device__ __half g_xh[(size_t)MM * DD];
__device__ __half g_yh[(size_t)MM * DD];
__device__ __half g_wh[4][(size_t)DD * DD];

#define SMEM_SWIZZLE_128B(off) ((off) ^ (((off) >> 3) & 0x70))

__device__ __forceinline__ uint32_t smem_u32(const void* p) {
    uint32_t a;
    asm("{ .reg .u64 t; cvta.to.shared.u64 t, %1; cvt.u32.u64 %0, t; }"
        : "=r"(a) : "l"(p));
    return a;
}
__device__ __forceinline__ void cp_async16(uint32_t saddr, const void* gaddr) {
    asm volatile("cp.async.cg.shared.global [%0], [%1], 16;"
                 :: "r"(saddr), "l"(gaddr) : "memory");
}
#define CP_COMMIT() asm volatile("cp.async.commit_group;" ::: "memory")
#define CP_WAIT1()  asm volatile("cp.async.wait_group 1;" ::: "memory")

__device__ __forceinline__ void ldm_x4(uint32_t* r, uint32_t addr) {
    asm volatile("ldmatrix.sync.aligned.m8n8.x4.shared.b16 {%0,%1,%2,%3}, [%4];"
                 : "=r"(r[0]), "=r"(r[1]), "=r"(r[2]), "=r"(r[3]) : "r"(addr));
}
__device__ __forceinline__ void ldm_x4_trans(uint32_t* r, uint32_t addr) {
    asm volatile("ldmatrix.sync.aligned.m8n8.x4.trans.shared.b16 {%0,%1,%2,%3}, [%4];"
                 : "=r"(r[0]), "=r"(r[1]), "=r"(r[2]), "=r"(r[3]) : "r"(addr));
}
__device__ __forceinline__ void mma16816(float* c, const uint32_t* a, const uint32_t* b) {
    asm volatile(
        "mma.sync.aligned.m16n8k16.row.col.f32.bf16.bf16.f32 "
        "{%0,%1,%2,%3}, {%4,%5,%6,%7}, {%8,%9}, {%0,%1,%2,%3};"
        : "+f"(c[0]), "+f"(c[1]), "+f"(c[2]), "+f"(c[3])
        : "r"(a[0]), "r"(a[1]), "r"(a[2]), "r"(a[3]), "r"(b[0]), "r"(b[1]));
}
__device__ __forceinline__ void mma16816h(float* c, const uint32_t* a, const uint32_t* b) {
    asm volatile(
        "mma.sync.aligned.m16n8k16.row.col.f32.f16.f16.f32 "
        "{%0,%1,%2,%3}, {%4,%5,%6,%7}, {%8,%9}, {%0,%1,%2,%3};"
        : "+f"(c[0]), "+f"(c[1]), "+f"(c[2]), "+f"(c[3])
        : "r"(a[0]), "r"(a[1]), "r"(a[2]), "r"(a[3]), "r"(b[0]), "r"(b[1]));
}
__device__ __forceinline__ float ex2f(float x) {
    float y; asm("ex2.approx.ftz.f32 %0, %1;" : "=f"(y) : "f"(x)); return y;
}
__device__ __forceinline__ uint32_t packbf(float lo, float hi) {
    uint32_t r;
    asm("cvt.rn.bf16x2.f32 %0, %1, %2;" : "=r"(r) : "f"(hi), "f"(lo));
    return r;
}

// ---------------- RoPE table (fp64 for accuracy) ----------------------------
__global__ void rope_table_kernel() {
    int idx = blockIdx.x * blockDim.x + threadIdx.x;
    if (idx >= SS * 32) return;
    int s = idx >> 5;
    int p = idx & 31;
    double invf = exp(-(double)p * (log(10000.0) / 32.0));
    double ang = (double)s * invf;
    g_cos[idx] = (float)cos(ang);
    g_sin[idx] = (float)sin(ang);
}

// ---------------- fused fp32 -> fp16 converts (x + 4 weights) ----------------
// 4 float4 per thread (MLP=4). Segments: 0..3 = weights (M4 float4 each),
// 4..5 = x (2*M4 float4 total; offset relative to seg 4 start).
#define M4 (DD * DD / 4)
__global__ void __launch_bounds__(256) convert_all_kernel(
    const float* __restrict__ x,  const float* __restrict__ Wq,
    const float* __restrict__ Wk, const float* __restrict__ Wv,
    const float* __restrict__ Wo)
{
    int id = blockIdx.x * blockDim.x + threadIdx.x;     // < 6*M4/4
    if (id >= 6 * M4 / 4) return;
    int base4 = id * 4;                                  // float4 index
    int seg = base4 / M4;                                // chunks never straddle
    const float* src;
    __half* dst;
    size_t off;
    if (seg < 4) {
        off = (size_t)(base4 - seg * M4);
        src = (seg == 0) ? Wq : (seg == 1) ? Wk : (seg == 2) ? Wv : Wo;
        dst = g_wh[seg];
    } else {
        off = (size_t)(base4 - 4 * M4);                  // x spans segs 4..5
        src = x;
        dst = g_xh;
    }
    float4 v[4];
#pragma unroll
    for (int j = 0; j < 4; j++)
        v[j] = *(const float4*)(src + (off + j) * 4);
#pragma unroll
    for (int j = 0; j < 4; j++) {
        uint2 u;
        u.x = (uint32_t)__half_as_ushort(__float2half(v[j].x)) |
              ((uint32_t)__half_as_ushort(__float2half(v[j].y)) << 16);
        u.y = (uint32_t)__half_as_ushort(__float2half(v[j].z)) |
              ((uint32_t)__half_as_ushort(__float2half(v[j].w)) << 16);
        *(uint2*)(dst + (off + j) * 4) = u;
    }
}

// ---------------- HMMA fp16 1-term GEMM, CTA 256x128, warp tile 64x64 --------
// FUSED=1: QKV — grid.z selects {Wq->rope->q16(x1/8), Wk->rope->k16,
//                                Wv->sigmoid->vb}; RoPE fused in epilogue.
// FUSED=0: O   — A=g_yh, W=g_wh[3], fp32 store to Cext with bias b0p.
#define KSTAGES 32
#define GSTAGE 49152u                // A 32KB (256x128B) + B 16KB (128x128B)
#define GEMM_SMEM (2 * GSTAGE)

template<int FUSED>
__global__ void __launch_bounds__(256, 1) gemm_tc_kernel(
    const float* __restrict__ b0p, const float* __restrict__ b1p,
    const float* __restrict__ b2p, float* __restrict__ Cext)
{
    extern __shared__ char smem[];
    const uint32_t sb = smem_u32(smem);
    const int tid  = threadIdx.x;
    const int wid  = tid >> 5;
    const int lane = tid & 31;
    const int n0 = blockIdx.x << 7;
    const int m0 = blockIdx.y << 8;          // 256-row tiles
    const int wm = (wid >> 1) * 64;          // 4 warp rows
    const int wn = (wid & 1) * 64;           // 2 warp cols (one head each)

    int mode, widx;
    const float* bias;
    if (FUSED) {
        widx = blockIdx.z;
        mode = widx + 1;
        bias = (widx == 0) ? b0p : (widx == 1) ? b1p : b2p;
    } else {
        widx = 3; mode = 0; bias = b0p;
    }

    const __half* __restrict__ Ah = FUSED ? g_xh : g_yh;
    const __half* __restrict__ Wh = g_wh[widx];

    float acc[4][8][4];
#pragma unroll
    for (int i = 0; i < 4; i++)
#pragma unroll
        for (int j = 0; j < 8; j++)
#pragma unroll
            for (int t = 0; t < 4; t++) acc[i][j][t] = 0.f;

    auto issue_stage = [&](int s) {
        uint32_t base = sb + (uint32_t)(s & 1) * GSTAGE;
#pragma unroll
        for (int i = 0; i < 8; i++) {
            int c   = tid + (i << 8);
            int row = c >> 3;
            int col = c & 7;
            uint32_t off = SMEM_SWIZZLE_128B((uint32_t)(row * 128 + col * 16));
            cp_async16(base + off,
                       Ah + (size_t)(m0 + row) * DD + s * 64 + col * 8);
        }
#pragma unroll
        for (int i = 0; i < 4; i++) {
            int c   = tid + (i << 8);
            int row = c >> 3;
            int col = c & 7;
            uint32_t off = SMEM_SWIZZLE_128B((uint32_t)(row * 128 + col * 16));
            cp_async16(base + 32768 + off,
                       Wh + (size_t)(n0 + row) * DD + s * 64 + col * 8);
        }
    };

    issue_stage(0); CP_COMMIT();
    issue_stage(1); CP_COMMIT();

    const int a_row = (lane & 15);
    const int a_colsel = (lane >> 4) << 4;
    const int b_row = (lane & 7) + ((lane >> 4) << 3);
    const int b_colsel = ((lane >> 3) & 1) << 4;

    for (int s = 0; s < KSTAGES; s++) {
        CP_WAIT1();
        __syncthreads();
        const uint32_t sA = sb + (uint32_t)(s & 1) * GSTAGE;
        const uint32_t sB = sA + 32768;

#pragma unroll
        for (int ks = 0; ks < 4; ks++) {
            uint32_t ah[4][4], bh[8][2];
#pragma unroll
            for (int mi = 0; mi < 4; mi++) {
                uint32_t rbase = (uint32_t)((wm + mi * 16 + a_row) * 128);
                ldm_x4(ah[mi], sA + SMEM_SWIZZLE_128B(rbase + ks * 32 + a_colsel));
            }
#pragma unroll
            for (int p = 0; p < 4; p++) {
                uint32_t brel = (uint32_t)((wn + p * 16 + b_row) * 128 + ks * 32 + b_colsel);
                uint32_t tb[4];
                ldm_x4(tb, sB + SMEM_SWIZZLE_128B(brel));
                bh[2*p][0] = tb[0]; bh[2*p][1] = tb[1];
                bh[2*p+1][0] = tb[2]; bh[2*p+1][1] = tb[3];
            }
#pragma unroll
            for (int mi = 0; mi < 4; mi++)
#pragma unroll
                for (int ni = 0; ni < 8; ni++)
                    mma16816h(acc[mi][ni], ah[mi], bh[ni]);
        }
        __syncthreads();
        if (s + 2 < KSTAGES) issue_stage(s + 2);
        CP_COMMIT();
    }

    // ---------------- epilogue ------------------------------------------------
    if (FUSED && mode <= 2) {
        __half* dst = (mode == 1) ? g_q16 : g_k16;
        const float qs = (mode == 1) ? 0.125f : 1.f;
#pragma unroll
        for (int mi = 0; mi < 4; mi++) {
#pragma unroll
            for (int half = 0; half < 2; half++) {
                int m = m0 + wm + mi * 16 + (lane >> 2) + half * 8;
                int bb = m >> 11, srow = m & (SS - 1);
#pragma unroll
                for (int ni = 0; ni < 4; ni++) {
                    int n = n0 + wn + ni * 8 + 2 * (lane & 3);
                    int hh = n >> 6, d = n & 63;
                    int ti = (srow << 5) + d;
                    float c0 = __ldg(g_cos + ti),     sn0 = __ldg(g_sin + ti);
                    float c1 = __ldg(g_cos + ti + 1), sn1 = __ldg(g_sin + ti + 1);
                    float a0 = acc[mi][ni][2*half]       + __ldg(bias + n);
                    float a1 = acc[mi][ni][2*half + 1]   + __ldg(bias + n + 1);
                    float e0 = acc[mi][ni+4][2*half]     + __ldg(bias + n + 32);
                    float e1 = acc[mi][ni+4][2*half + 1] + __ldg(bias + n + 33);
                    size_t o = ((size_t)(bb * HH + hh) * SS + srow) * DH + d;
                    *(__half2*)(dst + o) =
                        __floats2half2_rn((a0*c0 - e0*sn0) * qs, (a1*c1 - e1*sn1) * qs);
                    *(__half2*)(dst + o + 32) =
                        __floats2half2_rn((e0*c0 + a0*sn0) * qs, (e1*c1 + a1*sn1) * qs);
                }
            }
        }
    } else {
#pragma unroll
        for (int mi = 0; mi < 4; mi++) {
#pragma unroll
            for (int ni = 0; ni < 8; ni++) {
                int n = n0 + wn + ni * 8 + 2 * (lane & 3);
                float b0 = __ldg(bias + n);
                float b1 = __ldg(bias + n + 1);
#pragma unroll
                for (int half = 0; half < 2; half++) {
                    int m = m0 + wm + mi * 16 + (lane >> 2) + half * 8;
                    float v0 = acc[mi][ni][2 * half]     + b0;
                    float v1 = acc[mi][ni][2 * half + 1] + b1;
                    if (mode == 0) {
                        Cext[(size_t)m * DD + n]     = v0;
                        Cext[(size_t)m * DD + n + 1] = v1;
                    } else {   // mode 3: sigmoid -> vb
                        int bb = m >> 11, srow = m & (SS - 1);
                        int hh = n >> 6, d = n & 63;
                        size_t o = ((size_t)(bb * HH + hh) * SS + srow) * DH + d;
                        v0 = 1.f / (1.f + __expf(-v0));
                        v1 = 1.f / (1.f + __expf(-v1));
                        __nv_bfloat162 t2;
                        t2.x = __float2bfloat16(v0);
                        t2.y = __float2bfloat16(v1);
                        *(__nv_bfloat162*)(g_vb + o) = t2;
                    }
                }
            }
        }
    }
}

// ---------------- tensor-core flash attention --------------------------------
// CTA: 128 q rows, 128 threads; 4 warps x 32 rows (2 m-tiles of 16).
// Round-13 phase structure (full-tile QK -> batch exp -> full-tile PV: wide
// ILP through 16 independent s accumulators) + hoisted Q fragments +
// unmasked exp fast-path for interior tiles.
// QK: fp16 1-term; PV: bf16. smem: Q 16KB @0; tiles (k 8K|v 8K) dbl-buffered.
#define ATT_SMEM (16384 + 2 * 16384)
#define L2E 1.4426950408889634f
#define SH20 28.853900817779268f

__global__ void __launch_bounds__(128, 1) attn_tc_kernel() {
    extern __shared__ char smem[];
    const uint32_t sb = smem_u32(smem);
    const int tid  = threadIdx.x;
    const int wid  = tid >> 5;
    const int lane = tid & 31;
    const int bh = blockIdx.y;
    const int q0 = (gridDim.x - 1 - blockIdx.x) << 7;   // heavy CTAs first
    const int b  = bh >> 5;
    const int h  = bh & 31;
    const size_t rowbase = (size_t)bh * SS;
    const int wm = wid << 5;                 // 32 rows per warp

    auto issue_tile = [&](int t) {
        int j0 = t << 6;
        uint32_t base = sb + 16384 + (t & 1) * 16384;
#pragma unroll
        for (int i = 0; i < 4; i++) {
            int c = tid * 4 + i;
            int row = c >> 3, col = c & 7;
            uint32_t off = SMEM_SWIZZLE_128B((uint32_t)(row * 128 + col * 16));
            size_t g = (rowbase + j0 + row) * DH + col * 8;
            cp_async16(base + off,        g_k16 + g);
            cp_async16(base + 8192 + off, g_vb + g);
        }
    };

    // Q: 128 rows x 128B = 16KB, 1024 chunks, 8 per thread
#pragma unroll
    for (int i = 0; i < 8; i++) {
        int c = tid * 8 + i;
        int row = c >> 3, col = c & 7;
        uint32_t off = SMEM_SWIZZLE_128B((uint32_t)(row * 128 + col * 16));
        cp_async16(sb + off, g_q16 + (rowbase + q0 + row) * DH + col * 8);
    }
    issue_tile(0); CP_COMMIT();
    const int nt = (q0 >> 6) + 2;
    issue_tile(1); CP_COMMIT();

    float o[2][8][4];
#pragma unroll
    for (int mi = 0; mi < 2; mi++)
#pragma unroll
        for (int nf = 0; nf < 8; nf++)
#pragma unroll
            for (int i = 0; i < 4; i++) o[mi][nf][i] = 0.f;
    float l[2][2] = {{0.f, 0.f}, {0.f, 0.f}};

    const int a_rc  = (lane & 15) * 128 + ((lane >> 4) << 4);
    const int b_rc  = ((lane & 7) + ((lane >> 4) << 3)) * 128 + (((lane >> 3) & 1) << 4);
    const int v_rc  = (lane & 15) * 128 + ((lane >> 4) << 4);
    const int r0    = q0 + wm + (lane >> 2);     // m-tile 0 rows: r0, r0+8; tile 1: +16,+24

    uint32_t q4[2][4][4];          // hoisted Q fragments [mi][ks][4]
    bool qload = false;

    for (int t = 0; t < nt; t++) {
        CP_WAIT1();
        __syncthreads();
        if (!qload) {              // Q arrived with group0; load once
            qload = true;
#pragma unroll
            for (int mi = 0; mi < 2; mi++)
#pragma unroll
                for (int ks = 0; ks < 4; ks++)
                    ldm_x4(q4[mi][ks], sb + SMEM_SWIZZLE_128B(
                        (uint32_t)((wm + mi * 16) * 128 + a_rc + ks * 32)));
        }
        const uint32_t sK = sb + 16384 + (t & 1) * 16384;
        if ((t << 6) <= q0 + wm + 31) {
            // ---- full-tile QK (16 independent accumulators, wide ILP) ----
            float s[2][8][4];
#pragma unroll
            for (int mi = 0; mi < 2; mi++)
#pragma unroll
                for (int nf = 0; nf < 8; nf++)
#pragma unroll
                    for (int i = 0; i < 4; i++) s[mi][nf][i] = 0.f;

#pragma unroll
            for (int ks = 0; ks < 4; ks++) {
#pragma unroll
                for (int nb = 0; nb < 4; nb++) {
                    uint32_t kh4[4];
                    uint32_t brel = (uint32_t)(nb * 2048 + b_rc + ks * 32);
                    ldm_x4(kh4, sK + SMEM_SWIZZLE_128B(brel));
#pragma unroll
                    for (int mi = 0; mi < 2; mi++) {
                        mma16816h(s[mi][2*nb],   q4[mi][ks], &kh4[0]);
                        mma16816h(s[mi][2*nb+1], q4[mi][ks], &kh4[2]);
                    }
                }
            }

            // ---- batch exp + pack (unmasked fast path for interior tiles) ----
            const bool unmasked = ((t << 6) + 63 <= q0 + wm);
            uint32_t pk[2][8][2];
            const int jb = (t << 6) + ((lane & 3) << 1);
#pragma unroll
            for (int mi = 0; mi < 2; mi++) {
                int rm = r0 + mi * 16;
#pragma unroll
                for (int nf = 0; nf < 8; nf++) {
                    float p0, p1, p2, p3;
                    if (unmasked) {
                        p0 = ex2f(fmaf(s[mi][nf][0], L2E, -SH20));
                        p1 = ex2f(fmaf(s[mi][nf][1], L2E, -SH20));
                        p2 = ex2f(fmaf(s[mi][nf][2], L2E, -SH20));
                        p3 = ex2f(fmaf(s[mi][nf][3], L2E, -SH20));
                    } else {
                        int j = jb + nf * 8;
                        p0 = (j     <= rm)     ? ex2f(fmaf(s[mi][nf][0], L2E, -SH20)) : 0.f;
                        p1 = (j + 1 <= rm)     ? ex2f(fmaf(s[mi][nf][1], L2E, -SH20)) : 0.f;
                        p2 = (j     <= rm + 8) ? ex2f(fmaf(s[mi][nf][2], L2E, -SH20)) : 0.f;
                        p3 = (j + 1 <= rm + 8) ? ex2f(fmaf(s[mi][nf][3], L2E, -SH20)) : 0.f;
                    }
                    l[mi][0] += p0 + p1;
                    l[mi][1] += p2 + p3;
                    pk[mi][nf][0] = packbf(p0, p1);
                    pk[mi][nf][1] = packbf(p2, p3);
                }
            }

            // ---- full-tile PV ----
#pragma unroll
            for (int ks = 0; ks < 4; ks++) {
#pragma unroll
                for (int nb = 0; nb < 4; nb++) {
                    uint32_t vf[4];
                    uint32_t vrel = (uint32_t)(ks * 2048 + v_rc + nb * 32);
                    ldm_x4_trans(vf, sK + 8192 + SMEM_SWIZZLE_128B(vrel));
#pragma unroll
                    for (int mi = 0; mi < 2; mi++) {
                        uint32_t a[4] = {pk[mi][2*ks][0], pk[mi][2*ks][1],
                                         pk[mi][2*ks+1][0], pk[mi][2*ks+1][1]};
                        mma16816(o[mi][2*nb],   a, &vf[0]);
                        mma16816(o[mi][2*nb+1], a, &vf[2]);
                    }
                }
            }
        }
        __syncthreads();
        if (t + 2 < nt) issue_tile(t + 2);
        CP_COMMIT();
    }

#pragma unroll
    for (int mi = 0; mi < 2; mi++) {
        l[mi][0] += __shfl_xor_sync(0xffffffffu, l[mi][0], 1);
        l[mi][0] += __shfl_xor_sync(0xffffffffu, l[mi][0], 2);
        l[mi][1] += __shfl_xor_sync(0xffffffffu, l[mi][1], 1);
        l[mi][1] += __shfl_xor_sync(0xffffffffu, l[mi][1], 2);
        float inv0 = 1.f / l[mi][0], inv1 = 1.f / l[mi][1];
        int rm = r0 + mi * 16;
#pragma unroll
        for (int nf = 0; nf < 8; nf++) {
            int d = h * 64 + nf * 8 + ((lane & 3) << 1);
            __half2 w0 = __floats2half2_rn(o[mi][nf][0] * inv0, o[mi][nf][1] * inv0);
            __half2 w1 = __floats2half2_rn(o[mi][nf][2] * inv1, o[mi][nf][3] * inv1);
            *(__half2*)&g_yh[((size_t)b * SS + rm)     * DD + d] = w0;
            *(__half2*)&g_yh[((size_t)b * SS + rm + 8) * DD + d] = w1;
        }
    }
}

// ---------------- launch ------------------------------------------------------
extern "C" void kernel_launch(void* const* d_in, const int* in_sizes, int n_in,
                              void* d_out, int out_size) {
    (void)in_sizes; (void)n_in; (void)out_size;
    const float* x  = (const float*)d_in[0];
    const float* Wq = (const float*)d_in[1];
    const float* bq = (const float*)d_in[2];
    const float* Wk = (const float*)d_in[3];
    const float* bk = (const float*)d_in[4];
    const float* Wv = (const float*)d_in[5];
    const float* bv = (const float*)d_in[6];
    const float* Wo = (const float*)d_in[7];
    const float* bo = (const float*)d_in[8];
    float* out = (float*)d_out;

    cudaFuncSetAttribute((const void*)gemm_tc_kernel<1>,
                         cudaFuncAttributeMaxDynamicSharedMemorySize, GEMM_SMEM);
    cudaFuncSetAttribute((const void*)gemm_tc_kernel<0>,
                         cudaFuncAttributeMaxDynamicSharedMemorySize, GEMM_SMEM);
    cudaFuncSetAttribute((const void*)attn_tc_kernel,
                         cudaFuncAttributeMaxDynamicSharedMemorySize, ATT_SMEM);

    rope_table_kernel<<<(SS * 32 + 255) / 256, 256>>>();
    convert_all_kernel<<<(6 * M4 / 4 + 255) / 256, 256>>>(x, Wq, Wk, Wv, Wo);

    dim3 qkv_grid(DD / 128, MM / 256, 3);
    gemm_tc_kernel<1><<<qkv_grid, 256, GEMM_SMEM>>>(bq, bk, bv, nullptr);

    attn_tc_kernel<<<dim3(SS / 128, BB * HH), 128, ATT_SMEM>>>();

    dim3 o_grid(DD / 128, MM / 256, 1);
    gemm_tc_kernel<0><<<o_grid, 256, GEMM_SMEM>>>(bo, nullptr, nullptr, out);
}

// round 17
// speedup vs baseline: 1.0338x; 1.0225x over previous
#include <cuda_runtime.h>
#include <cuda_bf16.h>
#include <cuda_fp16.h>
#include <math.h>
#include <stdint.h>

#define BB 2
#define SS 2048
#define DD 2048
#define HH 32
#define DH 64
#define MM (BB*SS)   // 4096

// ---------------- scratch (device globals; no allocations allowed) ----------
__device__ float g_cos[SS*32];
__device__ float g_sin[SS*32];
// attention operands (fp16/bf16, head-transposed [B,H,S,Dh])
__device__ __half g_q16[(size_t)BB*HH*SS*DH];         // q (x1/8), roped
__device__ __half g_k16[(size_t)BB*HH*SS*DH];         // k, roped
__device__ __nv_bfloat16 g_vb[(size_t)BB*HH*SS*DH];   // sigmoid(v), bf16
// GEMM operands (plain fp16)
__device__ __half g_xh[(size_t)MM * DD];
__device__ __half g_yh[(size_t)MM * DD];
__device__ __half g_wh[4][(size_t)DD * DD];

#define SMEM_SWIZZLE_128B(off) ((off) ^ (((off) >> 3) & 0x70))

__device__ __forceinline__ uint32_t smem_u32(const void* p) {
    uint32_t a;
    asm("{ .reg .u64 t; cvta.to.shared.u64 t, %1; cvt.u32.u64 %0, t; }"
        : "=r"(a) : "l"(p));
    return a;
}
__device__ __forceinline__ void cp_async16(uint32_t saddr, const void* gaddr) {
    asm volatile("cp.async.cg.shared.global [%0], [%1], 16;"
                 :: "r"(saddr), "l"(gaddr) : "memory");
}
#define CP_COMMIT() asm volatile("cp.async.commit_group;" ::: "memory")
#define CP_WAIT1()  asm volatile("cp.async.wait_group 1;" ::: "memory")

__device__ __forceinline__ void ldm_x4(uint32_t* r, uint32_t addr) {
    asm volatile("ldmatrix.sync.aligned.m8n8.x4.shared.b16 {%0,%1,%2,%3}, [%4];"
                 : "=r"(r[0]), "=r"(r[1]), "=r"(r[2]), "=r"(r[3]) : "r"(addr));
}
__device__ __forceinline__ void ldm_x4_trans(uint32_t* r, uint32_t addr) {
    asm volatile("ldmatrix.sync.aligned.m8n8.x4.trans.shared.b16 {%0,%1,%2,%3}, [%4];"
                 : "=r"(r[0]), "=r"(r[1]), "=r"(r[2]), "=r"(r[3]) : "r"(addr));
}
__device__ __forceinline__ void mma16816(float* c, const uint32_t* a, const uint32_t* b) {
    asm volatile(
        "mma.sync.aligned.m16n8k16.row.col.f32.bf16.bf16.f32 "
        "{%0,%1,%2,%3}, {%4,%5,%6,%7}, {%8,%9}, {%0,%1,%2,%3};"
        : "+f"(c[0]), "+f"(c[1]), "+f"(c[2]), "+f"(c[3])
        : "r"(a[0]), "r"(a[1]), "r"(a[2]), "r"(a[3]), "r"(b[0]), "r"(b[1]));
}
__device__ __forceinline__ void mma16816h(float* c, const uint32_t* a, const uint32_t* b) {
    asm volatile(
        "mma.sync.aligned.m16n8k16.row.col.f32.f16.f16.f32 "
        "{%0,%1,%2,%3}, {%4,%5,%6,%7}, {%8,%9}, {%0,%1,%2,%3};"
        : "+f"(c[0]), "+f"(c[1]), "+f"(c[2]), "+f"(c[3])
        : "r"(a[0]), "r"(a[1]), "r"(a[2]), "r"(a[3]), "r"(b[0]), "r"(b[1]));
}
__device__ __forceinline__ float ex2f(float x) {
    float y; asm("ex2.approx.ftz.f32 %0, %1;" : "=f"(y) : "f"(x)); return y;
}
__device__ __forceinline__ uint32_t packbf(float lo, float hi) {
    uint32_t r;
    asm("cvt.rn.bf16x2.f32 %0, %1, %2;" : "=r"(r) : "f"(hi), "f"(lo));
    return r;
}

// ---------------- RoPE table (fp64 for accuracy) ----------------------------
__global__ void rope_table_kernel() {
    int idx = blockIdx.x * blockDim.x + threadIdx.x;
    if (idx >= SS * 32) return;
    int s = idx >> 5;
    int p = idx & 31;
    double invf = exp(-(double)p * (log(10000.0) / 32.0));
    double ang = (double)s * invf;
    g_cos[idx] = (float)cos(ang);
    g_sin[idx] = (float)sin(ang);
}

// ---------------- fused fp32 -> fp16 converts (x + 4 weights) ----------------
// 4 float4 per thread (MLP=4). Segments: 0..3 = weights (M4 float4 each),
// 4..5 = x (2*M4 float4 total; offset relative to seg 4 start).
#define M4 (DD * DD / 4)
__global__ void __launch_bounds__(256) convert_all_kernel(
    const float* __restrict__ x,  const float* __restrict__ Wq,
    const float* __restrict__ Wk, const float* __restrict__ Wv,
    const float* __restrict__ Wo)
{
    int id = blockIdx.x * blockDim.x + threadIdx.x;     // < 6*M4/4
    if (id >= 6 * M4 / 4) return;
    int base4 = id * 4;                                  // float4 index
    int seg = base4 / M4;                                // chunks never straddle
    const float* src;
    __half* dst;
    size_t off;
    if (seg < 4) {
        off = (size_t)(base4 - seg * M4);
        src = (seg == 0) ? Wq : (seg == 1) ? Wk : (seg == 2) ? Wv : Wo;
        dst = g_wh[seg];
    } else {
        off = (size_t)(base4 - 4 * M4);                  // x spans segs 4..5
        src = x;
        dst = g_xh;
    }
    float4 v[4];
#pragma unroll
    for (int j = 0; j < 4; j++)
        v[j] = *(const float4*)(src + (off + j) * 4);
#pragma unroll
    for (int j = 0; j < 4; j++) {
        uint2 u;
        u.x = (uint32_t)__half_as_ushort(__float2half(v[j].x)) |
              ((uint32_t)__half_as_ushort(__float2half(v[j].y)) << 16);
        u.y = (uint32_t)__half_as_ushort(__float2half(v[j].z)) |
              ((uint32_t)__half_as_ushort(__float2half(v[j].w)) << 16);
        *(uint2*)(dst + (off + j) * 4) = u;
    }
}

// ---------------- HMMA fp16 1-term GEMM, CTA 256x128, warp tile 64x64 --------
// FUSED=1: QKV — grid.z selects {Wq->rope->q16(x1/8), Wk->rope->k16,
//                                Wv->sigmoid->vb}; RoPE fused in epilogue.
// FUSED=0: O   — A=g_yh, W=g_wh[3], fp32 store to Cext with bias b0p.
#define KSTAGES 32
#define GSTAGE 49152u                // A 32KB (256x128B) + B 16KB (128x128B)
#define GEMM_SMEM (2 * GSTAGE)

template<int FUSED>
__global__ void __launch_bounds__(256, 1) gemm_tc_kernel(
    const float* __restrict__ b0p, const float* __restrict__ b1p,
    const float* __restrict__ b2p, float* __restrict__ Cext)
{
    extern __shared__ char smem[];
    const uint32_t sb = smem_u32(smem);
    const int tid  = threadIdx.x;
    const int wid  = tid >> 5;
    const int lane = tid & 31;
    const int n0 = blockIdx.x << 7;
    const int m0 = blockIdx.y << 8;          // 256-row tiles
    const int wm = (wid >> 1) * 64;          // 4 warp rows
    const int wn = (wid & 1) * 64;           // 2 warp cols (one head each)

    int mode, widx;
    const float* bias;
    if (FUSED) {
        widx = blockIdx.z;
        mode = widx + 1;
        bias = (widx == 0) ? b0p : (widx == 1) ? b1p : b2p;
    } else {
        widx = 3; mode = 0; bias = b0p;
    }

    const __half* __restrict__ Ah = FUSED ? g_xh : g_yh;
    const __half* __restrict__ Wh = g_wh[widx];

    float acc[4][8][4];
#pragma unroll
    for (int i = 0; i < 4; i++)
#pragma unroll
        for (int j = 0; j < 8; j++)
#pragma unroll
            for (int t = 0; t < 4; t++) acc[i][j][t] = 0.f;

    auto issue_stage = [&](int s) {
        uint32_t base = sb + (uint32_t)(s & 1) * GSTAGE;
#pragma unroll
        for (int i = 0; i < 8; i++) {
            int c   = tid + (i << 8);
            int row = c >> 3;
            int col = c & 7;
            uint32_t off = SMEM_SWIZZLE_128B((uint32_t)(row * 128 + col * 16));
            cp_async16(base + off,
                       Ah + (size_t)(m0 + row) * DD + s * 64 + col * 8);
        }
#pragma unroll
        for (int i = 0; i < 4; i++) {
            int c   = tid + (i << 8);
            int row = c >> 3;
            int col = c & 7;
            uint32_t off = SMEM_SWIZZLE_128B((uint32_t)(row * 128 + col * 16));
            cp_async16(base + 32768 + off,
                       Wh + (size_t)(n0 + row) * DD + s * 64 + col * 8);
        }
    };

    issue_stage(0); CP_COMMIT();
    issue_stage(1); CP_COMMIT();

    const int a_row = (lane & 15);
    const int a_colsel = (lane >> 4) << 4;
    const int b_row = (lane & 7) + ((lane >> 4) << 3);
    const int b_colsel = ((lane >> 3) & 1) << 4;

    for (int s = 0; s < KSTAGES; s++) {
        CP_WAIT1();
        __syncthreads();
        const uint32_t sA = sb + (uint32_t)(s & 1) * GSTAGE;
        const uint32_t sB = sA + 32768;

#pragma unroll
        for (int ks = 0; ks < 4; ks++) {
            uint32_t ah[4][4], bh[8][2];
#pragma unroll
            for (int mi = 0; mi < 4; mi++) {
                uint32_t rbase = (uint32_t)((wm + mi * 16 + a_row) * 128);
                ldm_x4(ah[mi], sA + SMEM_SWIZZLE_128B(rbase + ks * 32 + a_colsel));
            }
#pragma unroll
            for (int p = 0; p < 4; p++) {
                uint32_t brel = (uint32_t)((wn + p * 16 + b_row) * 128 + ks * 32 + b_colsel);
                uint32_t tb[4];
                ldm_x4(tb, sB + SMEM_SWIZZLE_128B(brel));
                bh[2*p][0] = tb[0]; bh[2*p][1] = tb[1];
                bh[2*p+1][0] = tb[2]; bh[2*p+1][1] = tb[3];
            }
#pragma unroll
            for (int mi = 0; mi < 4; mi++)
#pragma unroll
                for (int ni = 0; ni < 8; ni++)
                    mma16816h(acc[mi][ni], ah[mi], bh[ni]);
        }
        __syncthreads();
        if (s + 2 < KSTAGES) issue_stage(s + 2);
        CP_COMMIT();
    }

    // ---------------- epilogue ------------------------------------------------
    if (FUSED && mode <= 2) {
        __half* dst = (mode == 1) ? g_q16 : g_k16;
        const float qs = (mode == 1) ? 0.125f : 1.f;
#pragma unroll
        for (int mi = 0; mi < 4; mi++) {
#pragma unroll
            for (int half = 0; half < 2; half++) {
                int m = m0 + wm + mi * 16 + (lane >> 2) + half * 8;
                int bb = m >> 11, srow = m & (SS - 1);
#pragma unroll
                for (int ni = 0; ni < 4; ni++) {
                    int n = n0 + wn + ni * 8 + 2 * (lane & 3);
                    int hh = n >> 6, d = n & 63;
                    int ti = (srow << 5) + d;
                    float c0 = __ldg(g_cos + ti),     sn0 = __ldg(g_sin + ti);
                    float c1 = __ldg(g_cos + ti + 1), sn1 = __ldg(g_sin + ti + 1);
                    float a0 = acc[mi][ni][2*half]       + __ldg(bias + n);
                    float a1 = acc[mi][ni][2*half + 1]   + __ldg(bias + n + 1);
                    float e0 = acc[mi][ni+4][2*half]     + __ldg(bias + n + 32);
                    float e1 = acc[mi][ni+4][2*half + 1] + __ldg(bias + n + 33);
                    size_t o = ((size_t)(bb * HH + hh) * SS + srow) * DH + d;
                    *(__half2*)(dst + o) =
                        __floats2half2_rn((a0*c0 - e0*sn0) * qs, (a1*c1 - e1*sn1) * qs);
                    *(__half2*)(dst + o + 32) =
                        __floats2half2_rn((e0*c0 + a0*sn0) * qs, (e1*c1 + a1*sn1) * qs);
                }
            }
        }
    } else {
#pragma unroll
        for (int mi = 0; mi < 4; mi++) {
#pragma unroll
            for (int ni = 0; ni < 8; ni++) {
                int n = n0 + wn + ni * 8 + 2 * (lane & 3);
                float b0 = __ldg(bias + n);
                float b1 = __ldg(bias + n + 1);
#pragma unroll
                for (int half = 0; half < 2; half++) {
                    int m = m0 + wm + mi * 16 + (lane >> 2) + half * 8;
                    float v0 = acc[mi][ni][2 * half]     + b0;
                    float v1 = acc[mi][ni][2 * half + 1] + b1;
                    if (mode == 0) {
                        Cext[(size_t)m * DD + n]     = v0;
                        Cext[(size_t)m * DD + n + 1] = v1;
                    } else {   // mode 3: sigmoid -> vb
                        int bb = m >> 11, srow = m & (SS - 1);
                        int hh = n >> 6, d = n & 63;
                        size_t o = ((size_t)(bb * HH + hh) * SS + srow) * DH + d;
                        v0 = 1.f / (1.f + __expf(-v0));
                        v1 = 1.f / (1.f + __expf(-v1));
                        __nv_bfloat162 t2;
                        t2.x = __float2bfloat16(v0);
                        t2.y = __float2bfloat16(v1);
                        *(__nv_bfloat162*)(g_vb + o) = t2;
                    }
                }
            }
        }
    }
}

// ---------------- tensor-core flash attention (round-13 structure) -----------
// CTA: 128 q rows, 128 threads; 4 warps x 32 rows (2 m-tiles of 16).
// Full-tile QK -> batch exp -> full-tile PV; Q fragments re-loaded per tile.
// QK: fp16 1-term; PV: bf16. smem: Q 16KB @0; tiles (k 8K|v 8K) dbl-buffered.
#define ATT_SMEM (16384 + 2 * 16384)
#define L2E 1.4426950408889634f
#define SH20 28.853900817779268f

__global__ void __launch_bounds__(128, 1) attn_tc_kernel() {
    extern __shared__ char smem[];
    const uint32_t sb = smem_u32(smem);
    const int tid  = threadIdx.x;
    const int wid  = tid >> 5;
    const int lane = tid & 31;
    const int bh = blockIdx.y;
    const int q0 = (gridDim.x - 1 - blockIdx.x) << 7;   // heavy CTAs first
    const int b  = bh >> 5;
    const int h  = bh & 31;
    const size_t rowbase = (size_t)bh * SS;
    const int wm = wid << 5;                 // 32 rows per warp

    auto issue_tile = [&](int t) {
        int j0 = t << 6;
        uint32_t base = sb + 16384 + (t & 1) * 16384;
#pragma unroll
        for (int i = 0; i < 4; i++) {
            int c = tid * 4 + i;
            int row = c >> 3, col = c & 7;
            uint32_t off = SMEM_SWIZZLE_128B((uint32_t)(row * 128 + col * 16));
            size_t g = (rowbase + j0 + row) * DH + col * 8;
            cp_async16(base + off,        g_k16 + g);
            cp_async16(base + 8192 + off, g_vb + g);
        }
    };

    // Q: 128 rows x 128B = 16KB, 1024 chunks, 8 per thread
#pragma unroll
    for (int i = 0; i < 8; i++) {
        int c = tid * 8 + i;
        int row = c >> 3, col = c & 7;
        uint32_t off = SMEM_SWIZZLE_128B((uint32_t)(row * 128 + col * 16));
        cp_async16(sb + off, g_q16 + (rowbase + q0 + row) * DH + col * 8);
    }
    issue_tile(0); CP_COMMIT();
    const int nt = (q0 >> 6) + 2;
    issue_tile(1); CP_COMMIT();

    float o[2][8][4];
#pragma unroll
    for (int mi = 0; mi < 2; mi++)
#pragma unroll
        for (int nf = 0; nf < 8; nf++)
#pragma unroll
            for (int i = 0; i < 4; i++) o[mi][nf][i] = 0.f;
    float l[2][2] = {{0.f, 0.f}, {0.f, 0.f}};

    const int a_rc  = (lane & 15) * 128 + ((lane >> 4) << 4);
    const int b_rc  = ((lane & 7) + ((lane >> 4) << 3)) * 128 + (((lane >> 3) & 1) << 4);
    const int v_rc  = (lane & 15) * 128 + ((lane >> 4) << 4);
    const int r0    = q0 + wm + (lane >> 2);     // m-tile 0 rows: r0, r0+8; tile 1: +16,+24

    for (int t = 0; t < nt; t++) {
        CP_WAIT1();
        __syncthreads();
        const uint32_t sK = sb + 16384 + (t & 1) * 16384;
        if ((t << 6) <= q0 + wm + 31) {
            float s[2][8][4];
#pragma unroll
            for (int mi = 0; mi < 2; mi++)
#pragma unroll
                for (int nf = 0; nf < 8; nf++)
#pragma unroll
                    for (int i = 0; i < 4; i++) s[mi][nf][i] = 0.f;

#pragma unroll
            for (int ks = 0; ks < 4; ks++) {
                uint32_t q4[2][4];
#pragma unroll
                for (int mi = 0; mi < 2; mi++)
                    ldm_x4(q4[mi], sb + SMEM_SWIZZLE_128B(
                        (uint32_t)((wm + mi * 16) * 128 + a_rc + ks * 32)));
#pragma unroll
                for (int nb = 0; nb < 4; nb++) {
                    uint32_t kh4[4];
                    uint32_t brel = (uint32_t)(nb * 2048 + b_rc + ks * 32);
                    ldm_x4(kh4, sK + SMEM_SWIZZLE_128B(brel));
#pragma unroll
                    for (int mi = 0; mi < 2; mi++) {
                        mma16816h(s[mi][2*nb],   q4[mi], &kh4[0]);
                        mma16816h(s[mi][2*nb+1], q4[mi], &kh4[2]);
                    }
                }
            }

            uint32_t pk[2][8][2];
            const int jb = (t << 6) + ((lane & 3) << 1);
#pragma unroll
            for (int mi = 0; mi < 2; mi++) {
                int rm = r0 + mi * 16;
#pragma unroll
                for (int nf = 0; nf < 8; nf++) {
                    int j = jb + nf * 8;
                    float p0 = (j     <= rm)     ? ex2f(fmaf(s[mi][nf][0], L2E, -SH20)) : 0.f;
                    float p1 = (j + 1 <= rm)     ? ex2f(fmaf(s[mi][nf][1], L2E, -SH20)) : 0.f;
                    float p2 = (j     <= rm + 8) ? ex2f(fmaf(s[mi][nf][2], L2E, -SH20)) : 0.f;
                    float p3 = (j + 1 <= rm + 8) ? ex2f(fmaf(s[mi][nf][3], L2E, -SH20)) : 0.f;
                    l[mi][0] += p0 + p1;
                    l[mi][1] += p2 + p3;
                    pk[mi][nf][0] = packbf(p0, p1);
                    pk[mi][nf][1] = packbf(p2, p3);
                }
            }

#pragma unroll
            for (int ks = 0; ks < 4; ks++) {
#pragma unroll
                for (int nb = 0; nb < 4; nb++) {
                    uint32_t vf[4];
                    uint32_t vrel = (uint32_t)(ks * 2048 + v_rc + nb * 32);
                    ldm_x4_trans(vf, sK + 8192 + SMEM_SWIZZLE_128B(vrel));
#pragma unroll
                    for (int mi = 0; mi < 2; mi++) {
                        uint32_t a[4] = {pk[mi][2*ks][0], pk[mi][2*ks][1],
                                         pk[mi][2*ks+1][0], pk[mi][2*ks+1][1]};
                        mma16816(o[mi][2*nb],   a, &vf[0]);
                        mma16816(o[mi][2*nb+1], a, &vf[2]);
                    }
                }
            }
        }
        __syncthreads();
        if (t + 2 < nt) issue_tile(t + 2);
        CP_COMMIT();
    }

#pragma unroll
    for (int mi = 0; mi < 2; mi++) {
        l[mi][0] += __shfl_xor_sync(0xffffffffu, l[mi][0], 1);
        l[mi][0] += __shfl_xor_sync(0xffffffffu, l[mi][0], 2);
        l[mi][1] += __shfl_xor_sync(0xffffffffu, l[mi][1], 1);
        l[mi][1] += __shfl_xor_sync(0xffffffffu, l[mi][1], 2);
        float inv0 = 1.f / l[mi][0], inv1 = 1.f / l[mi][1];
        int rm = r0 + mi * 16;
#pragma unroll
        for (int nf = 0; nf < 8; nf++) {
            int d = h * 64 + nf * 8 + ((lane & 3) << 1);
            __half2 w0 = __floats2half2_rn(o[mi][nf][0] * inv0, o[mi][nf][1] * inv0);
            __half2 w1 = __floats2half2_rn(o[mi][nf][2] * inv1, o[mi][nf][3] * inv1);
            *(__half2*)&g_yh[((size_t)b * SS + rm)     * DD + d] = w0;
            *(__half2*)&g_yh[((size_t)b * SS + rm + 8) * DD + d] = w1;
        }
    }
}

// ---------------- launch ------------------------------------------------------
extern "C" void kernel_launch(void* const* d_in, const int* in_sizes, int n_in,
                              void* d_out, int out_size) {
    (void)in_sizes; (void)n_in; (void)out_size;
    const float* x  = (const float*)d_in[0];
    const float* Wq = (const float*)d_in[1];
    const float* bq = (const float*)d_in[2];
    const float* Wk = (const float*)d_in[3];
    const float* bk = (const float*)d_in[4];
    const float* Wv = (const float*)d_in[5];
    const float* bv = (const float*)d_in[6];
    const float* Wo = (const float*)d_in[7];
    const float* bo = (const float*)d_in[8];
    float* out = (float*)d_out;

    cudaFuncSetAttribute((const void*)gemm_tc_kernel<1>,
                         cudaFuncAttributeMaxDynamicSharedMemorySize, GEMM_SMEM);
    cudaFuncSetAttribute((const void*)gemm_tc_kernel<0>,
                         cudaFuncAttributeMaxDynamicSharedMemorySize, GEMM_SMEM);
    cudaFuncSetAttribute((const void*)attn_tc_kernel,
                         cudaFuncAttributeMaxDynamicSharedMemorySize, ATT_SMEM);

    rope_table_kernel<<<(SS * 32 + 255) / 256, 256>>>();
    convert_all_kernel<<<(6 * M4 / 4 + 255) / 256, 256>>>(x, Wq, Wk, Wv, Wo);

    dim3 qkv_grid(DD / 128, MM / 256, 3);
    gemm_tc_kernel<1><<<qkv_grid, 256, GEMM_SMEM>>>(bq, bk, bv, nullptr);

    attn_tc_kernel<<<dim3(SS / 128, BB * HH), 128, ATT_SMEM>>>();

    dim3 o_grid(DD / 128, MM / 256, 1);
    gemm_tc_kernel<0><<<o_grid, 256, GEMM_SMEM>>>(bo, nullptr, nullptr, out);
}